// round 1
// baseline (speedup 1.0000x reference)
#include <cuda_runtime.h>
#include <cuda_bf16.h>
#include <cstddef>

// Problem constants (fixed by the dataset)
#define NU_MAX 100000
#define NI_MAX 50000
#define DD 128

// ---------------- device scratch (no allocations allowed) ----------------
__device__ float g_sum_u[(size_t)NU_MAX * DD];
__device__ float g_sum_i[(size_t)NI_MAX * DD];
__device__ float g_h1u[(size_t)NU_MAX * DD];
__device__ float g_h1i[(size_t)NI_MAX * DD];
__device__ float g_cnt_u[NU_MAX];
__device__ float g_cnt_i[NI_MAX];
// 4 GEMM configs x 256 k-rows x 128 n-cols, layout [k][n]
// rows 0..127  : (Wr + LW)^T   (multiplies X)
// rows 128..255: Wl^T          (multiplies mean)
__device__ float g_wt[4 * 256 * 128];

// ---------------- weight transpose + combine ----------------
// dst[k*128 + n] = A[n*128 + k] (+ B[n*128 + k] if B != null)
__global__ void transpose_combine(float* __restrict__ dst,
                                  const float* __restrict__ A,
                                  const float* __restrict__ B) {
    __shared__ float tile[32][33];
    int bx = blockIdx.x;  // k tile
    int by = blockIdx.y;  // n tile
    int k = bx * 32 + threadIdx.x;
#pragma unroll
    for (int j = 0; j < 4; ++j) {
        int nl = threadIdx.y + j * 8;
        int n = by * 32 + nl;
        float v = A[n * 128 + k];
        if (B) v += B[n * 128 + k];
        tile[nl][threadIdx.x] = v;
    }
    __syncthreads();
#pragma unroll
    for (int j = 0; j < 4; ++j) {
        int kl = threadIdx.y + j * 8;
        dst[(bx * 32 + kl) * 128 + by * 32 + threadIdx.x] = tile[threadIdx.x][kl];
    }
}

// ---------------- edge scatter-add (one warp per edge) ----------------
__global__ void scatter_kernel(const float* __restrict__ feat,
                               const int* __restrict__ src,
                               const int* __restrict__ dst,
                               float* __restrict__ sum,
                               float* __restrict__ cnt, int E) {
    int w = (blockIdx.x * blockDim.x + threadIdx.x) >> 5;
    int lane = threadIdx.x & 31;
    if (w >= E) return;
    int s = __ldg(src + w);
    int d = __ldg(dst + w);
    float4 v = reinterpret_cast<const float4*>(feat + (size_t)s * DD)[lane];
    float4* p = reinterpret_cast<float4*>(sum + (size_t)d * DD) + lane;
    atomicAdd(p, v);  // vector red (sm_90+)
    if (cnt != nullptr && lane == 0) atomicAdd(cnt + d, 1.0f);
}

// ---------------- fused SAGE GEMM ----------------
// out[m,:] = act( X[m,:] @ Wc^T  +  (1/max(cnt[m],1)) * S[m,:] @ Wl^T  + b1 + b2 )
// Wt: [256][128], rows 0..127 = Wc^T, rows 128..255 = Wl^T
#define GEMM_SMEM_FLOATS (256 * 128 + 2 * 128 * 16 + 256)
#define GEMM_SMEM_BYTES (GEMM_SMEM_FLOATS * 4)

__global__ __launch_bounds__(256, 1)
void sage_gemm(const float* __restrict__ X, const float* __restrict__ S,
               const float* __restrict__ cnt, const float* __restrict__ Wt,
               const float* __restrict__ b1, const float* __restrict__ b2,
               float* __restrict__ out, int nrows, int do_relu) {
    extern __shared__ float sm[];
    float* Ws = sm;                      // 256*128
    float* As = sm + 256 * 128;          // 2 * 128*16
    float* scs = As + 2 * 128 * 16;      // 128
    float* bss = scs + 128;              // 128

    const int tid = threadIdx.x;
    const int tx = tid & 15;
    const int ty = tid >> 4;
    const int m0 = blockIdx.x * 128;

    // weights: coalesced float4 copy, conflict-free
    {
        const float4* srcp = reinterpret_cast<const float4*>(Wt);
        float4* dstp = reinterpret_cast<float4*>(Ws);
#pragma unroll
        for (int i = 0; i < 32; ++i) dstp[tid + i * 256] = srcp[tid + i * 256];
    }
    if (tid < 128) {
        float c = 1.0f;
        if (m0 + tid < nrows) c = cnt[m0 + tid];
        scs[tid] = 1.0f / fmaxf(c, 1.0f);
        bss[tid] = b1[tid] + b2[tid];
    }

    float acc[8][8];
#pragma unroll
    for (int r = 0; r < 8; ++r)
#pragma unroll
        for (int j = 0; j < 8; ++j) acc[r][j] = 0.0f;

    float4 pf[2];

    auto loadChunk = [&](int c) {
        const float* srcp = (c < 8) ? X : S;
        int kc = (c & 7) * 16;
#pragma unroll
        for (int h = 0; h < 2; ++h) {
            int f = tid + h * 256;
            int m = f >> 2, c4 = f & 3;
            float4 v = make_float4(0.f, 0.f, 0.f, 0.f);
            if (m0 + m < nrows)
                v = *reinterpret_cast<const float4*>(&srcp[(size_t)(m0 + m) * DD + kc + c4 * 4]);
            pf[h] = v;
        }
    };
    auto storeChunk = [&](int c, int buf) {
#pragma unroll
        for (int h = 0; h < 2; ++h) {
            int f = tid + h * 256;
            int m = f >> 2, c4 = f & 3;
            float4 v = pf[h];
            if (c >= 8) {
                float s = scs[m];
                v.x *= s; v.y *= s; v.z *= s; v.w *= s;
            }
            *reinterpret_cast<float4*>(&As[buf * 2048 + m * 16 + c4 * 4]) = v;
        }
    };

    loadChunk(0);
    storeChunk(0, 0);
    __syncthreads();

    for (int c = 0; c < 16; ++c) {
        int buf = c & 1;
        if (c + 1 < 16) loadChunk(c + 1);
        int kbase = c * 16;
#pragma unroll
        for (int kk4 = 0; kk4 < 4; ++kk4) {
            float4 a[8];
#pragma unroll
            for (int r = 0; r < 8; ++r) {
                int m = ((r & 4) << 4) + 4 * ty + (r & 3);
                a[r] = *reinterpret_cast<const float4*>(&As[buf * 2048 + m * 16 + kk4 * 4]);
            }
#pragma unroll
            for (int q = 0; q < 4; ++q) {
                int k = kbase + kk4 * 4 + q;
                float4 w0 = *reinterpret_cast<const float4*>(&Ws[k * 128 + 4 * tx]);
                float4 w1 = *reinterpret_cast<const float4*>(&Ws[k * 128 + 64 + 4 * tx]);
                float wv[8] = {w0.x, w0.y, w0.z, w0.w, w1.x, w1.y, w1.z, w1.w};
#pragma unroll
                for (int r = 0; r < 8; ++r) {
                    float av = (q == 0) ? a[r].x : (q == 1) ? a[r].y : (q == 2) ? a[r].z : a[r].w;
#pragma unroll
                    for (int j = 0; j < 8; ++j) acc[r][j] = fmaf(av, wv[j], acc[r][j]);
                }
            }
        }
        if (c + 1 < 16) {
            storeChunk(c + 1, 1 - buf);
            __syncthreads();
        }
    }

    // epilogue: bias (+ optional relu), guarded store
#pragma unroll
    for (int r = 0; r < 8; ++r) {
        int m = ((r & 4) << 4) + 4 * ty + (r & 3);
        if (m0 + m >= nrows) continue;
        float* orow = out + (size_t)(m0 + m) * DD;
#pragma unroll
        for (int jh = 0; jh < 2; ++jh) {
            int n = jh * 64 + 4 * tx;
            float4 v;
            v.x = acc[r][jh * 4 + 0] + bss[n + 0];
            v.y = acc[r][jh * 4 + 1] + bss[n + 1];
            v.z = acc[r][jh * 4 + 2] + bss[n + 2];
            v.w = acc[r][jh * 4 + 3] + bss[n + 3];
            if (do_relu) {
                v.x = fmaxf(v.x, 0.f); v.y = fmaxf(v.y, 0.f);
                v.z = fmaxf(v.z, 0.f); v.w = fmaxf(v.w, 0.f);
            }
            *reinterpret_cast<float4*>(&orow[n]) = v;
        }
    }
}

// ---------------- host orchestration ----------------
extern "C" void kernel_launch(void* const* d_in, const int* in_sizes, int n_in,
                              void* d_out, int out_size) {
    const float* x_user = (const float*)d_in[0];
    const float* x_item = (const float*)d_in[1];
    const int* ui_src = (const int*)d_in[2];
    const int* ui_dst = (const int*)d_in[3];
    const int* iu_src = (const int*)d_in[4];
    const int* iu_dst = (const int*)d_in[5];
    const float* W1l_ui = (const float*)d_in[6];
    const float* b1_ui  = (const float*)d_in[7];
    const float* W1r_ui = (const float*)d_in[8];
    const float* W1l_iu = (const float*)d_in[9];
    const float* b1_iu  = (const float*)d_in[10];
    const float* W1r_iu = (const float*)d_in[11];
    const float* L1W_u  = (const float*)d_in[12];
    const float* L1b_u  = (const float*)d_in[13];
    const float* L1W_i  = (const float*)d_in[14];
    const float* L1b_i  = (const float*)d_in[15];
    const float* W2l_ui = (const float*)d_in[16];
    const float* b2_ui  = (const float*)d_in[17];
    const float* W2r_ui = (const float*)d_in[18];
    const float* W2l_iu = (const float*)d_in[19];
    const float* b2_iu  = (const float*)d_in[20];
    const float* W2r_iu = (const float*)d_in[21];
    const float* L2W_u  = (const float*)d_in[22];
    const float* L2b_u  = (const float*)d_in[23];
    const float* L2W_i  = (const float*)d_in[24];
    const float* L2b_i  = (const float*)d_in[25];

    const int NU = in_sizes[0] / DD;
    const int NI = in_sizes[1] / DD;
    const int E = in_sizes[2];

    float *sum_u, *sum_i, *h1u, *h1i, *cnt_u, *cnt_i, *wt;
    cudaGetSymbolAddress((void**)&sum_u, g_sum_u);
    cudaGetSymbolAddress((void**)&sum_i, g_sum_i);
    cudaGetSymbolAddress((void**)&h1u, g_h1u);
    cudaGetSymbolAddress((void**)&h1i, g_h1i);
    cudaGetSymbolAddress((void**)&cnt_u, g_cnt_u);
    cudaGetSymbolAddress((void**)&cnt_i, g_cnt_i);
    cudaGetSymbolAddress((void**)&wt, g_wt);

    cudaFuncSetAttribute(sage_gemm, cudaFuncAttributeMaxDynamicSharedMemorySize,
                         GEMM_SMEM_BYTES);

    float* out_u = (float*)d_out;
    float* out_i = out_u + (size_t)NU * DD;

    // weight prep: transpose + combine into g_wt
    dim3 tb(32, 8), tg(4, 4);
    transpose_combine<<<tg, tb>>>(wt + 0 * 32768,         W1r_iu, L1W_u);
    transpose_combine<<<tg, tb>>>(wt + 0 * 32768 + 16384, W1l_iu, nullptr);
    transpose_combine<<<tg, tb>>>(wt + 1 * 32768,         W1r_ui, L1W_i);
    transpose_combine<<<tg, tb>>>(wt + 1 * 32768 + 16384, W1l_ui, nullptr);
    transpose_combine<<<tg, tb>>>(wt + 2 * 32768,         W2r_iu, L2W_u);
    transpose_combine<<<tg, tb>>>(wt + 2 * 32768 + 16384, W2l_iu, nullptr);
    transpose_combine<<<tg, tb>>>(wt + 3 * 32768,         W2r_ui, L2W_i);
    transpose_combine<<<tg, tb>>>(wt + 3 * 32768 + 16384, W2l_ui, nullptr);

    cudaMemsetAsync(sum_u, 0, (size_t)NU * DD * sizeof(float));
    cudaMemsetAsync(sum_i, 0, (size_t)NI * DD * sizeof(float));
    cudaMemsetAsync(cnt_u, 0, (size_t)NU * sizeof(float));
    cudaMemsetAsync(cnt_i, 0, (size_t)NI * sizeof(float));

    int sblocks = (E * 32 + 255) / 256;
    // layer 1 aggregation (also computes degree counts; edges identical both layers)
    scatter_kernel<<<sblocks, 256>>>(x_item, iu_src, iu_dst, sum_u, cnt_u, E);
    scatter_kernel<<<sblocks, 256>>>(x_user, ui_src, ui_dst, sum_i, cnt_i, E);

    int gu = (NU + 127) / 128, gi = (NI + 127) / 128;
    sage_gemm<<<gu, 256, GEMM_SMEM_BYTES>>>(x_user, sum_u, cnt_u, wt + 0 * 32768,
                                            b1_iu, L1b_u, h1u, NU, 1);
    sage_gemm<<<gi, 256, GEMM_SMEM_BYTES>>>(x_item, sum_i, cnt_i, wt + 1 * 32768,
                                            b1_ui, L1b_i, h1i, NI, 1);

    // layer 2 aggregation
    cudaMemsetAsync(sum_u, 0, (size_t)NU * DD * sizeof(float));
    cudaMemsetAsync(sum_i, 0, (size_t)NI * DD * sizeof(float));
    scatter_kernel<<<sblocks, 256>>>(h1i, iu_src, iu_dst, sum_u, nullptr, E);
    scatter_kernel<<<sblocks, 256>>>(h1u, ui_src, ui_dst, sum_i, nullptr, E);

    sage_gemm<<<gu, 256, GEMM_SMEM_BYTES>>>(h1u, sum_u, cnt_u, wt + 2 * 32768,
                                            b2_iu, L2b_u, out_u, NU, 0);
    sage_gemm<<<gi, 256, GEMM_SMEM_BYTES>>>(h1i, sum_i, cnt_i, wt + 3 * 32768,
                                            b2_ui, L2b_i, out_i, NI, 0);
}

// round 6
// speedup vs baseline: 1.9780x; 1.9780x over previous
#include <cuda_runtime.h>
#include <cuda_bf16.h>
#include <cstdint>
#include <cstddef>

// Problem constants (fixed by the dataset)
#define NU_MAX 100000
#define NI_MAX 50000
#define E_MAX 300000
#define DD 128
#define SCAN_B 1024

// ---------------- device scratch (no allocations allowed) ----------------
__device__ float g_sum_u[(size_t)NU_MAX * DD];
__device__ float g_sum_i[(size_t)NI_MAX * DD];
__device__ float g_h1u[(size_t)NU_MAX * DD];
__device__ float g_h1i[(size_t)NI_MAX * DD];
__device__ int g_deg_u[NU_MAX];
__device__ int g_deg_i[NI_MAX];
__device__ int g_off_u[NU_MAX + 1];
__device__ int g_off_i[NI_MAX + 1];
__device__ int g_cur_u[NU_MAX];
__device__ int g_cur_i[NI_MAX];
__device__ int g_adj_u[E_MAX];   // src item ids per user dst (iu graph)
__device__ int g_adj_i[E_MAX];   // src user ids per item dst (ui graph)
__device__ int g_bsum[256];
// bf16 hi/lo weights, 4 cfgs. Per cfg: [2 hl][32 kb][128 n][8 k] bf16 = 65536 bf16.
__device__ __align__(16) __nv_bfloat16 g_wtb[4 * 65536];

// ---------------- weight prep: combine + bf16 hi/lo split + block layout ----
__global__ void prep_weights(__nv_bfloat16* __restrict__ dst,
                             const float* __restrict__ Wr,
                             const float* __restrict__ LW,
                             const float* __restrict__ Wl) {
    int kb = blockIdx.x;
    int t = threadIdx.x;
#pragma unroll
    for (int i = 0; i < 4; ++i) {
        int e = i * 256 + t;
        int n = e >> 3, kd = e & 7;
        int k = kb * 8 + kd;
        float v;
        if (k < 128) v = Wr[n * 128 + k] + LW[n * 128 + k];
        else         v = Wl[n * 128 + (k - 128)];
        __nv_bfloat16 h = __float2bfloat16_rn(v);
        float r = v - __bfloat162float(h);
        dst[kb * 1024 + e] = h;
        dst[32768 + kb * 1024 + e] = __float2bfloat16_rn(r);
    }
}

// ---------------- CSR build ----------------
__global__ void count_deg(const int* __restrict__ iu_dst, const int* __restrict__ ui_dst,
                          int E, int* __restrict__ degU, int* __restrict__ degI) {
    int i = blockIdx.x * blockDim.x + threadIdx.x;
    if (i < E) atomicAdd(&degU[iu_dst[i]], 1);
    else { i -= E; if (i < E) atomicAdd(&degI[ui_dst[i]], 1); }
}

__global__ void scan_part(const int* __restrict__ degU, int nU,
                          const int* __restrict__ degI, int nI,
                          int* __restrict__ offU, int* __restrict__ offI,
                          int* __restrict__ bsum, int nbU) {
    __shared__ int warp_s[32];
    int b = blockIdx.x;
    const int* deg; int* off; int n; int idx0;
    if (b < nbU) { deg = degU; off = offU; n = nU; idx0 = b * SCAN_B; }
    else         { deg = degI; off = offI; n = nI; idx0 = (b - nbU) * SCAN_B; }
    int i = idx0 + threadIdx.x;
    int v = (i < n) ? deg[i] : 0;
    int lane = threadIdx.x & 31, wrp = threadIdx.x >> 5;
    int inc = v;
#pragma unroll
    for (int o = 1; o < 32; o <<= 1) {
        int t = __shfl_up_sync(0xffffffffu, inc, o);
        if (lane >= o) inc += t;
    }
    if (lane == 31) warp_s[wrp] = inc;
    __syncthreads();
    if (wrp == 0) {
        int wv = warp_s[lane];
#pragma unroll
        for (int o = 1; o < 32; o <<= 1) {
            int t = __shfl_up_sync(0xffffffffu, wv, o);
            if (lane >= o) wv += t;
        }
        warp_s[lane] = wv;
    }
    __syncthreads();
    int base = (wrp > 0) ? warp_s[wrp - 1] : 0;
    int excl = base + inc - v;
    if (i < n) off[i] = excl;                 // partial (pre block-base)
    if (threadIdx.x == SCAN_B - 1) bsum[b] = base + inc;  // block total
}

__global__ void scan_top(int* __restrict__ bsum, int nbU, int nbI,
                         int* __restrict__ offU, int nU,
                         int* __restrict__ offI, int nI) {
    if (threadIdx.x == 0) {
        int acc = 0;
        for (int i = 0; i < nbU; ++i) { int t = bsum[i]; bsum[i] = acc; acc += t; }
        offU[nU] = acc;
    }
    if (threadIdx.x == 1) {
        int acc = 0;
        for (int i = nbU; i < nbU + nbI; ++i) { int t = bsum[i]; bsum[i] = acc; acc += t; }
        offI[nI] = acc;
    }
}

__global__ void scan_add(int* __restrict__ offU, int* __restrict__ curU, int nU,
                         int* __restrict__ offI, int* __restrict__ curI, int nI,
                         const int* __restrict__ bsum, int nbU) {
    int i = blockIdx.x * blockDim.x + threadIdx.x;
    if (i < nU) {
        int v = offU[i] + bsum[i / SCAN_B];
        offU[i] = v; curU[i] = v;
    } else {
        i -= nU;
        if (i < nI) {
            int v = offI[i] + bsum[nbU + i / SCAN_B];
            offI[i] = v; curI[i] = v;
        }
    }
}

__global__ void fill_adj(const int* __restrict__ iu_src, const int* __restrict__ iu_dst,
                         const int* __restrict__ ui_src, const int* __restrict__ ui_dst,
                         int E, int* __restrict__ curU, int* __restrict__ adjU,
                         int* __restrict__ curI, int* __restrict__ adjI) {
    int i = blockIdx.x * blockDim.x + threadIdx.x;
    if (i < E) {
        int p = atomicAdd(&curU[iu_dst[i]], 1);
        adjU[p] = iu_src[i];
    } else {
        i -= E;
        if (i < E) {
            int p = atomicAdd(&curI[ui_dst[i]], 1);
            adjI[p] = ui_src[i];
        }
    }
}

// ---------------- gather aggregation (one warp per dst node; 2 graphs fused)
__global__ void gather_agg2(const float* __restrict__ srcU, const int* __restrict__ adjU,
                            const int* __restrict__ offU, float* __restrict__ outU, int nU,
                            const float* __restrict__ srcI, const int* __restrict__ adjI,
                            const int* __restrict__ offI, float* __restrict__ outI, int nI) {
    int w = (blockIdx.x * blockDim.x + threadIdx.x) >> 5;
    int lane = threadIdx.x & 31;
    const float* feat; const int* adj; const int* off; float* out; int d;
    if (w < nU) { feat = srcU; adj = adjU; off = offU; out = outU; d = w; }
    else {
        w -= nU;
        if (w >= nI) return;
        feat = srcI; adj = adjI; off = offI; out = outI; d = w;
    }
    int beg = __ldg(off + d), end = __ldg(off + d + 1);
    float4 acc = make_float4(0.f, 0.f, 0.f, 0.f);
    for (int base = beg; base < end; base += 32) {
        int sl = (base + lane < end) ? __ldg(adj + base + lane) : 0;
        int n = min(32, end - base);
        for (int j = 0; j < n; ++j) {
            int s = __shfl_sync(0xffffffffu, sl, j);
            float4 v = *(const float4*)(feat + (size_t)s * DD + lane * 4);
            acc.x += v.x; acc.y += v.y; acc.z += v.z; acc.w += v.w;
        }
    }
    *(float4*)(out + (size_t)d * DD + lane * 4) = acc;
}

// ---------------- tensor-core fused SAGE GEMM ----------------
// out[m,:] = act( X[m,:] @ Wc^T  +  (1/max(deg[m],1)) * S[m,:] @ Wl^T  + b1 + b2 )
__device__ __forceinline__ void ldsm4(uint32_t* r, const void* p) {
    uint32_t a = (uint32_t)__cvta_generic_to_shared(p);
    asm volatile("ldmatrix.sync.aligned.m8n8.x4.shared.b16 {%0,%1,%2,%3}, [%4];\n"
                 : "=r"(r[0]), "=r"(r[1]), "=r"(r[2]), "=r"(r[3]) : "r"(a));
}
__device__ __forceinline__ void mma16816(float* c, const uint32_t* a, const uint32_t* b) {
    asm volatile("mma.sync.aligned.m16n8k16.row.col.f32.bf16.bf16.f32 "
                 "{%0,%1,%2,%3}, {%4,%5,%6,%7}, {%8,%9}, {%0,%1,%2,%3};\n"
                 : "+f"(c[0]), "+f"(c[1]), "+f"(c[2]), "+f"(c[3])
                 : "r"(a[0]), "r"(a[1]), "r"(a[2]), "r"(a[3]), "r"(b[0]), "r"(b[1]));
}

#define SM_BYTES 66560

__global__ __launch_bounds__(256, 1)
void sage_gemm_tc(const float* __restrict__ X, const float* __restrict__ S,
                  const int* __restrict__ deg, const __nv_bfloat16* __restrict__ Wt,
                  const float* __restrict__ b1, const float* __restrict__ b2,
                  float* __restrict__ out, int nrows, int do_relu) {
    extern __shared__ char sm_raw[];
    __nv_bfloat16* Wsm = (__nv_bfloat16*)sm_raw;             // 2 * 8192 bf16
    __nv_bfloat16* Asm = (__nv_bfloat16*)(sm_raw + 32768);   // 2 * 8192 bf16
    float* scs = (float*)(sm_raw + 65536);
    float* bss = (float*)(sm_raw + 66048);

    const int tid = threadIdx.x;
    const int lane = tid & 31;
    const int wid = tid >> 5;
    const int m0w = (wid & 3) * 32;
    const int n0w = (wid >> 2) * 64;
    const int m0 = blockIdx.x * 128;

    const int sel = lane >> 3, lr = lane & 7;
    const int a_ro = ((sel & 1) << 3) + lr;
    const int a_kb = sel >> 1;
    const int b_ro = ((sel >> 1) << 3) + lr;
    const int b_kb = sel & 1;

    const int lm = tid >> 1;
    const int lh = tid & 1;

    if (tid < 128) {
        int c = (m0 + tid < nrows) ? deg[m0 + tid] : 1;
        scs[tid] = 1.0f / fmaxf((float)c, 1.0f);
        bss[tid] = b1[tid] + b2[tid];
    }

    float acc[2][8][4];
#pragma unroll
    for (int i = 0; i < 2; ++i)
#pragma unroll
        for (int j = 0; j < 8; ++j)
#pragma unroll
            for (int q = 0; q < 4; ++q) acc[i][j][q] = 0.f;

    float4 pfW[4], pfA[4];

    auto loadRegs = [&](int c) {
        const float4* sh = (const float4*)(Wt + c * 4096);
        const float4* sl = (const float4*)(Wt + 32768 + c * 4096);
        pfW[0] = sh[tid]; pfW[1] = sh[tid + 256];
        pfW[2] = sl[tid]; pfW[3] = sl[tid + 256];
        const float* src = (c < 4) ? X : S;
        int kc = (c & 3) * 32;
        if (m0 + lm < nrows) {
            const float* row = src + (size_t)(m0 + lm) * DD + kc + lh * 16;
#pragma unroll
            for (int j = 0; j < 4; ++j) pfA[j] = *(const float4*)(row + j * 4);
        } else {
#pragma unroll
            for (int j = 0; j < 4; ++j) pfA[j] = make_float4(0.f, 0.f, 0.f, 0.f);
        }
    };

    auto storeRegs = [&](int c, int stage) {
        float4* dh = (float4*)(Wsm + stage * 8192);
        dh[tid] = pfW[0]; dh[tid + 256] = pfW[1];
        float4* dl = (float4*)(Wsm + stage * 8192 + 4096);
        dl[tid] = pfW[2]; dl[tid + 256] = pfW[3];
        float s = (c >= 4) ? scs[lm] : 1.0f;
        __nv_bfloat16* ab = Asm + stage * 8192;
#pragma unroll
        for (int j = 0; j < 4; ++j) {
            int c0 = lh * 16 + j * 4;
            int kb = c0 >> 3, off = c0 & 7;
            float4 v = pfA[j];
            v.x *= s; v.y *= s; v.z *= s; v.w *= s;
            __nv_bfloat16 hx = __float2bfloat16_rn(v.x);
            __nv_bfloat16 hy = __float2bfloat16_rn(v.y);
            __nv_bfloat16 hz = __float2bfloat16_rn(v.z);
            __nv_bfloat16 hw = __float2bfloat16_rn(v.w);
            __nv_bfloat162 p0; p0.x = hx; p0.y = hy;
            __nv_bfloat162 p1; p1.x = hz; p1.y = hw;
            int idx = (kb * 128 + lm) * 8 + off;
            *(__nv_bfloat162*)(ab + idx) = p0;
            *(__nv_bfloat162*)(ab + idx + 2) = p1;
            __nv_bfloat162 q0, q1;
            q0.x = __float2bfloat16_rn(v.x - __bfloat162float(hx));
            q0.y = __float2bfloat16_rn(v.y - __bfloat162float(hy));
            q1.x = __float2bfloat16_rn(v.z - __bfloat162float(hz));
            q1.y = __float2bfloat16_rn(v.w - __bfloat162float(hw));
            *(__nv_bfloat162*)(ab + 4096 + idx) = q0;
            *(__nv_bfloat162*)(ab + 4096 + idx + 2) = q1;
        }
    };

    loadRegs(0);
    storeRegs(0, 0);
    __syncthreads();

    for (int c = 0; c < 8; ++c) {
        int stage = c & 1;
        if (c < 7) loadRegs(c + 1);
#pragma unroll
        for (int kk = 0; kk < 2; ++kk) {
            uint32_t ah[2][4], al[2][4], bh[4][4], bl[4][4];
#pragma unroll
            for (int mt = 0; mt < 2; ++mt) {
                const __nv_bfloat16* p = Asm + stage * 8192 +
                    (((2 * kk + a_kb) * 128) + m0w + mt * 16 + a_ro) * 8;
                ldsm4(ah[mt], p);
                ldsm4(al[mt], p + 4096);
            }
#pragma unroll
            for (int ng = 0; ng < 4; ++ng) {
                const __nv_bfloat16* p = Wsm + stage * 8192 +
                    (((2 * kk + b_kb) * 128) + n0w + ng * 16 + b_ro) * 8;
                ldsm4(bh[ng], p);
                ldsm4(bl[ng], p + 4096);
            }
#pragma unroll
            for (int mt = 0; mt < 2; ++mt)
#pragma unroll
                for (int nt = 0; nt < 8; ++nt) {
                    const uint32_t* pbh = &bh[nt >> 1][(nt & 1) * 2];
                    const uint32_t* pbl = &bl[nt >> 1][(nt & 1) * 2];
                    mma16816(acc[mt][nt], ah[mt], pbh);
                    mma16816(acc[mt][nt], al[mt], pbh);
                    mma16816(acc[mt][nt], ah[mt], pbl);
                }
        }
        if (c < 7) { storeRegs(c + 1, 1 - stage); __syncthreads(); }
    }

#pragma unroll
    for (int mt = 0; mt < 2; ++mt) {
        int rbase = m0w + mt * 16 + (lane >> 2);
#pragma unroll
        for (int half = 0; half < 2; ++half) {
            int r = rbase + half * 8;
            if (m0 + r >= nrows) continue;
            float* orow = out + (size_t)(m0 + r) * DD;
#pragma unroll
            for (int nt = 0; nt < 8; ++nt) {
                int col = n0w + nt * 8 + (lane & 3) * 2;
                float v0 = acc[mt][nt][half * 2 + 0] + bss[col];
                float v1 = acc[mt][nt][half * 2 + 1] + bss[col + 1];
                if (do_relu) { v0 = fmaxf(v0, 0.f); v1 = fmaxf(v1, 0.f); }
                *(float2*)(orow + col) = make_float2(v0, v1);
            }
        }
    }
}

// ---------------- host orchestration ----------------
extern "C" void kernel_launch(void* const* d_in, const int* in_sizes, int n_in,
                              void* d_out, int out_size) {
    const float* x_user = (const float*)d_in[0];
    const float* x_item = (const float*)d_in[1];
    const int* ui_src = (const int*)d_in[2];
    const int* ui_dst = (const int*)d_in[3];
    const int* iu_src = (const int*)d_in[4];
    const int* iu_dst = (const int*)d_in[5];
    const float* W1l_ui = (const float*)d_in[6];
    const float* b1_ui  = (const float*)d_in[7];
    const float* W1r_ui = (const float*)d_in[8];
    const float* W1l_iu = (const float*)d_in[9];
    const float* b1_iu  = (const float*)d_in[10];
    const float* W1r_iu = (const float*)d_in[11];
    const float* L1W_u  = (const float*)d_in[12];
    const float* L1b_u  = (const float*)d_in[13];
    const float* L1W_i  = (const float*)d_in[14];
    const float* L1b_i  = (const float*)d_in[15];
    const float* W2l_ui = (const float*)d_in[16];
    const float* b2_ui  = (const float*)d_in[17];
    const float* W2r_ui = (const float*)d_in[18];
    const float* W2l_iu = (const float*)d_in[19];
    const float* b2_iu  = (const float*)d_in[20];
    const float* W2r_iu = (const float*)d_in[21];
    const float* L2W_u  = (const float*)d_in[22];
    const float* L2b_u  = (const float*)d_in[23];
    const float* L2W_i  = (const float*)d_in[24];
    const float* L2b_i  = (const float*)d_in[25];

    const int NU = in_sizes[0] / DD;
    const int NI = in_sizes[1] / DD;
    const int E = in_sizes[2];

    float *sum_u, *sum_i, *h1u, *h1i;
    int *deg_u, *deg_i, *off_u, *off_i, *cur_u, *cur_i, *adj_u, *adj_i, *bsum;
    __nv_bfloat16* wtb;
    cudaGetSymbolAddress((void**)&sum_u, g_sum_u);
    cudaGetSymbolAddress((void**)&sum_i, g_sum_i);
    cudaGetSymbolAddress((void**)&h1u, g_h1u);
    cudaGetSymbolAddress((void**)&h1i, g_h1i);
    cudaGetSymbolAddress((void**)&deg_u, g_deg_u);
    cudaGetSymbolAddress((void**)&deg_i, g_deg_i);
    cudaGetSymbolAddress((void**)&off_u, g_off_u);
    cudaGetSymbolAddress((void**)&off_i, g_off_i);
    cudaGetSymbolAddress((void**)&cur_u, g_cur_u);
    cudaGetSymbolAddress((void**)&cur_i, g_cur_i);
    cudaGetSymbolAddress((void**)&adj_u, g_adj_u);
    cudaGetSymbolAddress((void**)&adj_i, g_adj_i);
    cudaGetSymbolAddress((void**)&bsum, g_bsum);
    cudaGetSymbolAddress((void**)&wtb, g_wtb);

    cudaFuncSetAttribute(sage_gemm_tc, cudaFuncAttributeMaxDynamicSharedMemorySize,
                         SM_BYTES);

    float* out_u = (float*)d_out;
    float* out_i = out_u + (size_t)NU * DD;

    // weight prep (bf16 hi/lo in ldmatrix block layout)
    prep_weights<<<32, 256>>>(wtb + 0 * 65536, W1r_iu, L1W_u, W1l_iu);
    prep_weights<<<32, 256>>>(wtb + 1 * 65536, W1r_ui, L1W_i, W1l_ui);
    prep_weights<<<32, 256>>>(wtb + 2 * 65536, W2r_iu, L2W_u, W2l_iu);
    prep_weights<<<32, 256>>>(wtb + 3 * 65536, W2r_ui, L2W_i, W2l_ui);

    // CSR build (once per launch; shared by both layers)
    cudaMemsetAsync(deg_u, 0, NU * sizeof(int));
    cudaMemsetAsync(deg_i, 0, NI * sizeof(int));
    count_deg<<<(2 * E + 255) / 256, 256>>>(iu_dst, ui_dst, E, deg_u, deg_i);
    int nbU = (NU + SCAN_B - 1) / SCAN_B, nbI = (NI + SCAN_B - 1) / SCAN_B;
    scan_part<<<nbU + nbI, SCAN_B>>>(deg_u, NU, deg_i, NI, off_u, off_i, bsum, nbU);
    scan_top<<<1, 32>>>(bsum, nbU, nbI, off_u, NU, off_i, NI);
    scan_add<<<(NU + NI + 255) / 256, 256>>>(off_u, cur_u, NU, off_i, cur_i, NI, bsum, nbU);
    fill_adj<<<(2 * E + 255) / 256, 256>>>(iu_src, iu_dst, ui_src, ui_dst, E,
                                           cur_u, adj_u, cur_i, adj_i);

    int gblocks = ((NU + NI) * 32 + 255) / 256;
    // layer 1 aggregation (gather, no atomics)
    gather_agg2<<<gblocks, 256>>>(x_item, adj_u, off_u, sum_u, NU,
                                  x_user, adj_i, off_i, sum_i, NI);

    int gu = (NU + 127) / 128, gi = (NI + 127) / 128;
    sage_gemm_tc<<<gu, 256, SM_BYTES>>>(x_user, sum_u, deg_u, wtb + 0 * 65536,
                                        b1_iu, L1b_u, h1u, NU, 1);
    sage_gemm_tc<<<gi, 256, SM_BYTES>>>(x_item, sum_i, deg_i, wtb + 1 * 65536,
                                        b1_ui, L1b_i, h1i, NI, 1);

    // layer 2 aggregation
    gather_agg2<<<gblocks, 256>>>(h1i, adj_u, off_u, sum_u, NU,
                                  h1u, adj_i, off_i, sum_i, NI);

    sage_gemm_tc<<<gu, 256, SM_BYTES>>>(h1u, sum_u, deg_u, wtb + 2 * 65536,
                                        b2_iu, L2b_u, out_u, NU, 0);
    sage_gemm_tc<<<gi, 256, SM_BYTES>>>(h1i, sum_i, deg_i, wtb + 3 * 65536,
                                        b2_ui, L2b_i, out_i, NI, 0);
}

// round 8
// speedup vs baseline: 2.2915x; 1.1585x over previous
#include <cuda_runtime.h>
#include <cuda_bf16.h>
#include <cstdint>
#include <cstddef>

// Problem constants (fixed by the dataset)
#define NU_MAX 100000
#define NI_MAX 50000
#define E_MAX 300000
#define DD 128
#define SCAN_B 1024

// ---------------- device scratch (no allocations allowed) ----------------
__device__ float g_sum_u[(size_t)NU_MAX * DD];
__device__ float g_sum_i[(size_t)NI_MAX * DD];
__device__ float g_h1u[(size_t)NU_MAX * DD];
__device__ float g_h1i[(size_t)NI_MAX * DD];
__device__ int g_deg_u[NU_MAX];
__device__ int g_deg_i[NI_MAX];
__device__ int g_off_u[NU_MAX + 1];
__device__ int g_off_i[NI_MAX + 1];
__device__ int g_cur_u[NU_MAX];
__device__ int g_cur_i[NI_MAX];
__device__ int g_adj_u[E_MAX];
__device__ int g_adj_i[E_MAX];
__device__ int g_bsum[256];
// bf16 hi/lo weights, 4 cfgs. Per cfg: [2 hl][32 kb][128 n][8 k] bf16 = 65536 bf16.
// k global 0..127 = (Wr+LW)^T (X side), 128..255 = Wl^T (mean side).
__device__ __align__(16) __nv_bfloat16 g_wtb[4 * 65536];

// ---------------- weight prep: combine + bf16 hi/lo split + block layout ----
__global__ void prep_weights(__nv_bfloat16* __restrict__ dst,
                             const float* __restrict__ Wr,
                             const float* __restrict__ LW,
                             const float* __restrict__ Wl) {
    int kb = blockIdx.x;
    int t = threadIdx.x;
#pragma unroll
    for (int i = 0; i < 4; ++i) {
        int e = i * 256 + t;
        int n = e >> 3, kd = e & 7;
        int k = kb * 8 + kd;
        float v;
        if (k < 128) v = Wr[n * 128 + k] + LW[n * 128 + k];
        else         v = Wl[n * 128 + (k - 128)];
        __nv_bfloat16 h = __float2bfloat16_rn(v);
        float r = v - __bfloat162float(h);
        dst[kb * 1024 + e] = h;
        dst[32768 + kb * 1024 + e] = __float2bfloat16_rn(r);
    }
}

// ---------------- CSR build ----------------
__global__ void count_deg(const int* __restrict__ iu_dst, const int* __restrict__ ui_dst,
                          int E, int* __restrict__ degU, int* __restrict__ degI) {
    int i = blockIdx.x * blockDim.x + threadIdx.x;
    if (i < E) atomicAdd(&degU[iu_dst[i]], 1);
    else { i -= E; if (i < E) atomicAdd(&degI[ui_dst[i]], 1); }
}

__global__ void scan_part(const int* __restrict__ degU, int nU,
                          const int* __restrict__ degI, int nI,
                          int* __restrict__ offU, int* __restrict__ offI,
                          int* __restrict__ bsum, int nbU) {
    __shared__ int warp_s[32];
    int b = blockIdx.x;
    const int* deg; int* off; int n; int idx0;
    if (b < nbU) { deg = degU; off = offU; n = nU; idx0 = b * SCAN_B; }
    else         { deg = degI; off = offI; n = nI; idx0 = (b - nbU) * SCAN_B; }
    int i = idx0 + threadIdx.x;
    int v = (i < n) ? deg[i] : 0;
    int lane = threadIdx.x & 31, wrp = threadIdx.x >> 5;
    int inc = v;
#pragma unroll
    for (int o = 1; o < 32; o <<= 1) {
        int t = __shfl_up_sync(0xffffffffu, inc, o);
        if (lane >= o) inc += t;
    }
    if (lane == 31) warp_s[wrp] = inc;
    __syncthreads();
    if (wrp == 0) {
        int wv = warp_s[lane];
#pragma unroll
        for (int o = 1; o < 32; o <<= 1) {
            int t = __shfl_up_sync(0xffffffffu, wv, o);
            if (lane >= o) wv += t;
        }
        warp_s[lane] = wv;
    }
    __syncthreads();
    int base = (wrp > 0) ? warp_s[wrp - 1] : 0;
    int excl = base + inc - v;
    if (i < n) off[i] = excl;
    if (threadIdx.x == SCAN_B - 1) bsum[b] = base + inc;
}

__global__ void scan_top(int* __restrict__ bsum, int nbU, int nbI,
                         int* __restrict__ offU, int nU,
                         int* __restrict__ offI, int nI) {
    if (threadIdx.x == 0) {
        int acc = 0;
        for (int i = 0; i < nbU; ++i) { int t = bsum[i]; bsum[i] = acc; acc += t; }
        offU[nU] = acc;
    }
    if (threadIdx.x == 1) {
        int acc = 0;
        for (int i = nbU; i < nbU + nbI; ++i) { int t = bsum[i]; bsum[i] = acc; acc += t; }
        offI[nI] = acc;
    }
}

__global__ void scan_add(int* __restrict__ offU, int* __restrict__ curU, int nU,
                         int* __restrict__ offI, int* __restrict__ curI, int nI,
                         const int* __restrict__ bsum, int nbU) {
    int i = blockIdx.x * blockDim.x + threadIdx.x;
    if (i < nU) {
        int v = offU[i] + bsum[i / SCAN_B];
        offU[i] = v; curU[i] = v;
    } else {
        i -= nU;
        if (i < nI) {
            int v = offI[i] + bsum[nbU + i / SCAN_B];
            offI[i] = v; curI[i] = v;
        }
    }
}

__global__ void fill_adj(const int* __restrict__ iu_src, const int* __restrict__ iu_dst,
                         const int* __restrict__ ui_src, const int* __restrict__ ui_dst,
                         int E, int* __restrict__ curU, int* __restrict__ adjU,
                         int* __restrict__ curI, int* __restrict__ adjI) {
    int i = blockIdx.x * blockDim.x + threadIdx.x;
    if (i < E) {
        int p = atomicAdd(&curU[iu_dst[i]], 1);
        adjU[p] = iu_src[i];
    } else {
        i -= E;
        if (i < E) {
            int p = atomicAdd(&curI[ui_dst[i]], 1);
            adjI[p] = ui_src[i];
        }
    }
}

// ---------------- gather aggregation (one warp per dst; MLP=4 unrolled) -----
__global__ void gather_agg2(const float* __restrict__ srcU, const int* __restrict__ adjU,
                            const int* __restrict__ offU, float* __restrict__ outU, int nU,
                            const float* __restrict__ srcI, const int* __restrict__ adjI,
                            const int* __restrict__ offI, float* __restrict__ outI, int nI) {
    int w = (blockIdx.x * blockDim.x + threadIdx.x) >> 5;
    int lane = threadIdx.x & 31;
    const float* feat; const int* adj; const int* off; float* out; int d;
    if (w < nU) { feat = srcU; adj = adjU; off = offU; out = outU; d = w; }
    else {
        w -= nU;
        if (w >= nI) return;
        feat = srcI; adj = adjI; off = offI; out = outI; d = w;
    }
    int beg = __ldg(off + d), end = __ldg(off + d + 1);
    float4 a0 = make_float4(0.f, 0.f, 0.f, 0.f);
    float4 a1 = make_float4(0.f, 0.f, 0.f, 0.f);
    int base = beg;
    for (; base + 4 <= end; base += 4) {
        int s0 = __ldg(adj + base + 0);
        int s1 = __ldg(adj + base + 1);
        int s2 = __ldg(adj + base + 2);
        int s3 = __ldg(adj + base + 3);
        float4 v0 = *(const float4*)(feat + (size_t)s0 * DD + lane * 4);
        float4 v1 = *(const float4*)(feat + (size_t)s1 * DD + lane * 4);
        float4 v2 = *(const float4*)(feat + (size_t)s2 * DD + lane * 4);
        float4 v3 = *(const float4*)(feat + (size_t)s3 * DD + lane * 4);
        a0.x += v0.x + v1.x; a0.y += v0.y + v1.y;
        a0.z += v0.z + v1.z; a0.w += v0.w + v1.w;
        a1.x += v2.x + v3.x; a1.y += v2.y + v3.y;
        a1.z += v2.z + v3.z; a1.w += v2.w + v3.w;
    }
    for (; base < end; ++base) {
        int s = __ldg(adj + base);
        float4 v = *(const float4*)(feat + (size_t)s * DD + lane * 4);
        a0.x += v.x; a0.y += v.y; a0.z += v.z; a0.w += v.w;
    }
    a0.x += a1.x; a0.y += a1.y; a0.z += a1.z; a0.w += a1.w;
    *(float4*)(out + (size_t)d * DD + lane * 4) = a0;
}

// ---------------- tensor-core fused SAGE GEMM (mma.sync, 512 threads) ------
// out[m,:] = act( X[m,:] @ Wc^T + (1/max(deg,1)) * S[m,:] @ Wl^T + b1 + b2 )
// bf16 split: acc += AhBh + AlBh + AhBl (fp32 accum)
__device__ __forceinline__ void ldsm4(uint32_t* r, const void* p) {
    uint32_t a = (uint32_t)__cvta_generic_to_shared(p);
    asm volatile("ldmatrix.sync.aligned.m8n8.x4.shared.b16 {%0,%1,%2,%3}, [%4];\n"
                 : "=r"(r[0]), "=r"(r[1]), "=r"(r[2]), "=r"(r[3]) : "r"(a));
}
__device__ __forceinline__ void mma16816(float* c, const uint32_t* a, const uint32_t* b) {
    asm volatile("mma.sync.aligned.m16n8k16.row.col.f32.bf16.bf16.f32 "
                 "{%0,%1,%2,%3}, {%4,%5,%6,%7}, {%8,%9}, {%0,%1,%2,%3};\n"
                 : "+f"(c[0]), "+f"(c[1]), "+f"(c[2]), "+f"(c[3])
                 : "r"(a[0]), "r"(a[1]), "r"(a[2]), "r"(a[3]), "r"(b[0]), "r"(b[1]));
}
__device__ __forceinline__ void cp_async16(void* smem_dst, const void* gsrc) {
    uint32_t a = (uint32_t)__cvta_generic_to_shared(smem_dst);
    asm volatile("cp.async.cg.shared.global [%0], [%1], 16;\n"
                 :: "r"(a), "l"(gsrc) : "memory");
}
#define CP_ASYNC_COMMIT() asm volatile("cp.async.commit_group;\n" ::: "memory")
#define CP_ASYNC_WAIT0()  asm volatile("cp.async.wait_group 0;\n" ::: "memory")

// smem: W 2 stages x (hi 4096 + lo 4096) bf16 = 32768 B
//       A 2 stages x (hi 4096 + lo 4096) bf16 = 32768 B
//       scs 128 f32, bss 128 f32
#define SM_BYTES 66560

__global__ __launch_bounds__(512, 1)
void sage_gemm_tc(const float* __restrict__ X, const float* __restrict__ S,
                  const int* __restrict__ deg, const __nv_bfloat16* __restrict__ Wt,
                  const float* __restrict__ b1, const float* __restrict__ b2,
                  float* __restrict__ out, int nrows, int do_relu) {
    extern __shared__ char sm_raw[];
    __nv_bfloat16* Wsm = (__nv_bfloat16*)sm_raw;             // 2 * 8192 bf16
    __nv_bfloat16* Asm = (__nv_bfloat16*)(sm_raw + 32768);   // 2 * 8192 bf16
    float* scs = (float*)(sm_raw + 65536);
    float* bss = (float*)(sm_raw + 66048);

    const int tid = threadIdx.x;
    const int lane = tid & 31;
    const int wid = tid >> 5;              // 0..15
    const int m0w = (wid & 3) * 32;        // warp m-origin
    const int n0w = (wid >> 2) * 32;       // warp n-origin
    const int m0 = blockIdx.x * 128;

    // ldmatrix per-lane geometry
    const int sel = lane >> 3, lr = lane & 7;
    const int a_ro = ((sel & 1) << 3) + lr;   // A frag rows
    const int a_kb = sel >> 1;
    const int b_ro = ((sel >> 1) << 3) + lr;  // B frag rows
    const int b_kb = sel & 1;

    const int arow = tid >> 2;   // A loader: row 0..127
    const int aq = tid & 3;      // A loader: 8-float quarter (one kb)

    if (tid < 128) {
        int c = (m0 + tid < nrows) ? deg[m0 + tid] : 1;
        scs[tid] = 1.0f / fmaxf((float)c, 1.0f);
        bss[tid] = b1[tid] + b2[tid];
    }

    float acc[2][4][4];
#pragma unroll
    for (int i = 0; i < 2; ++i)
#pragma unroll
        for (int j = 0; j < 4; ++j)
#pragma unroll
            for (int q = 0; q < 4; ++q) acc[i][j][q] = 0.f;

    float4 pfA[2];

    // W chunk c -> stage st via cp.async (hi 8KB + lo 8KB; 512 thr x 16B each)
    auto loadW = [&](int c, int st) {
        const char* sh = (const char*)(Wt + c * 4096) + tid * 16;
        const char* sl = (const char*)(Wt + 32768 + c * 4096) + tid * 16;
        char* dh = (char*)(Wsm + st * 8192) + tid * 16;
        char* dl = (char*)(Wsm + st * 8192 + 4096) + tid * 16;
        cp_async16(dh, sh);
        cp_async16(dl, sl);
        CP_ASYNC_COMMIT();
    };
    // A chunk c: load 8 floats into regs
    auto loadA = [&](int c) {
        const float* src = (c < 4) ? X : S;
        int kc = (c & 3) * 32 + aq * 8;
        if (m0 + arow < nrows) {
            const float* row = src + (size_t)(m0 + arow) * DD + kc;
            pfA[0] = *(const float4*)(row);
            pfA[1] = *(const float4*)(row + 4);
        } else {
            pfA[0] = make_float4(0.f, 0.f, 0.f, 0.f);
            pfA[1] = make_float4(0.f, 0.f, 0.f, 0.f);
        }
    };
    // A: convert + store into swizz-free block layout [kb 4][row 128][kd 8]
    auto storeA = [&](int c, int st) {
        float s = (c >= 4) ? scs[arow] : 1.0f;
        __nv_bfloat16* ab = Asm + st * 8192;
        int idx = (aq * 128 + arow) * 8;  // bf16 index; 16B aligned
        uint32_t hv[4], lv[4];
#pragma unroll
        for (int h = 0; h < 2; ++h) {
            float4 v = pfA[h];
            v.x *= s; v.y *= s; v.z *= s; v.w *= s;
            __nv_bfloat162 h0 = __floats2bfloat162_rn(v.x, v.y);
            __nv_bfloat162 h1 = __floats2bfloat162_rn(v.z, v.w);
            hv[h * 2 + 0] = *(uint32_t*)&h0;
            hv[h * 2 + 1] = *(uint32_t*)&h1;
            __nv_bfloat162 l0 = __floats2bfloat162_rn(v.x - __bfloat162float(h0.x),
                                                      v.y - __bfloat162float(h0.y));
            __nv_bfloat162 l1 = __floats2bfloat162_rn(v.z - __bfloat162float(h1.x),
                                                      v.w - __bfloat162float(h1.y));
            lv[h * 2 + 0] = *(uint32_t*)&l0;
            lv[h * 2 + 1] = *(uint32_t*)&l1;
        }
        *(uint4*)(ab + idx) = make_uint4(hv[0], hv[1], hv[2], hv[3]);
        *(uint4*)(ab + 4096 + idx) = make_uint4(lv[0], lv[1], lv[2], lv[3]);
    };

    loadW(0, 0);
    loadA(0);
    storeA(0, 0);
    CP_ASYNC_WAIT0();
    __syncthreads();

    for (int c = 0; c < 8; ++c) {
        int st = c & 1;
        if (c < 7) { loadW(c + 1, 1 - st); loadA(c + 1); }
#pragma unroll
        for (int kk = 0; kk < 2; ++kk) {
            uint32_t ah[2][4], al[2][4], bh[2][4], bl[2][4];
#pragma unroll
            for (int mt = 0; mt < 2; ++mt) {
                const __nv_bfloat16* p = Asm + st * 8192 +
                    (((2 * kk + a_kb) * 128) + m0w + mt * 16 + a_ro) * 8;
                ldsm4(ah[mt], p);
                ldsm4(al[mt], p + 4096);
            }
#pragma unroll
            for (int ng = 0; ng < 2; ++ng) {
                const __nv_bfloat16* p = Wsm + st * 8192 +
                    (((2 * kk + b_kb) * 128) + n0w + ng * 16 + b_ro) * 8;
                ldsm4(bh[ng], p);
                ldsm4(bl[ng], p + 4096);
            }
#pragma unroll
            for (int mt = 0; mt < 2; ++mt)
#pragma unroll
                for (int nt = 0; nt < 4; ++nt) {
                    const uint32_t* pbh = &bh[nt >> 1][(nt & 1) * 2];
                    const uint32_t* pbl = &bl[nt >> 1][(nt & 1) * 2];
                    mma16816(acc[mt][nt], ah[mt], pbh);
                    mma16816(acc[mt][nt], al[mt], pbh);
                    mma16816(acc[mt][nt], ah[mt], pbl);
                }
        }
        if (c < 7) {
            storeA(c + 1, 1 - st);
            CP_ASYNC_WAIT0();
            __syncthreads();
        }
    }

    // epilogue: bias (+ optional relu), guarded float2 stores
#pragma unroll
    for (int mt = 0; mt < 2; ++mt) {
        int rbase = m0w + mt * 16 + (lane >> 2);
#pragma unroll
        for (int half = 0; half < 2; ++half) {
            int r = rbase + half * 8;
            if (m0 + r >= nrows) continue;
            float* orow = out + (size_t)(m0 + r) * DD;
#pragma unroll
            for (int nt = 0; nt < 4; ++nt) {
                int col = n0w + nt * 8 + (lane & 3) * 2;
                float v0 = acc[mt][nt][half * 2 + 0] + bss[col];
                float v1 = acc[mt][nt][half * 2 + 1] + bss[col + 1];
                if (do_relu) { v0 = fmaxf(v0, 0.f); v1 = fmaxf(v1, 0.f); }
                *(float2*)(orow + col) = make_float2(v0, v1);
            }
        }
    }
}

// ---------------- host orchestration ----------------
extern "C" void kernel_launch(void* const* d_in, const int* in_sizes, int n_in,
                              void* d_out, int out_size) {
    const float* x_user = (const float*)d_in[0];
    const float* x_item = (const float*)d_in[1];
    const int* ui_src = (const int*)d_in[2];
    const int* ui_dst = (const int*)d_in[3];
    const int* iu_src = (const int*)d_in[4];
    const int* iu_dst = (const int*)d_in[5];
    const float* W1l_ui = (const float*)d_in[6];
    const float* b1_ui  = (const float*)d_in[7];
    const float* W1r_ui = (const float*)d_in[8];
    const float* W1l_iu = (const float*)d_in[9];
    const float* b1_iu  = (const float*)d_in[10];
    const float* W1r_iu = (const float*)d_in[11];
    const float* L1W_u  = (const float*)d_in[12];
    const float* L1b_u  = (const float*)d_in[13];
    const float* L1W_i  = (const float*)d_in[14];
    const float* L1b_i  = (const float*)d_in[15];
    const float* W2l_ui = (const float*)d_in[16];
    const float* b2_ui  = (const float*)d_in[17];
    const float* W2r_ui = (const float*)d_in[18];
    const float* W2l_iu = (const float*)d_in[19];
    const float* b2_iu  = (const float*)d_in[20];
    const float* W2r_iu = (const float*)d_in[21];
    const float* L2W_u  = (const float*)d_in[22];
    const float* L2b_u  = (const float*)d_in[23];
    const float* L2W_i  = (const float*)d_in[24];
    const float* L2b_i  = (const float*)d_in[25];

    const int NU = in_sizes[0] / DD;
    const int NI = in_sizes[1] / DD;
    const int E = in_sizes[2];

    float *sum_u, *sum_i, *h1u, *h1i;
    int *deg_u, *deg_i, *off_u, *off_i, *cur_u, *cur_i, *adj_u, *adj_i, *bsum;
    __nv_bfloat16* wtb;
    cudaGetSymbolAddress((void**)&sum_u, g_sum_u);
    cudaGetSymbolAddress((void**)&sum_i, g_sum_i);
    cudaGetSymbolAddress((void**)&h1u, g_h1u);
    cudaGetSymbolAddress((void**)&h1i, g_h1i);
    cudaGetSymbolAddress((void**)&deg_u, g_deg_u);
    cudaGetSymbolAddress((void**)&deg_i, g_deg_i);
    cudaGetSymbolAddress((void**)&off_u, g_off_u);
    cudaGetSymbolAddress((void**)&off_i, g_off_i);
    cudaGetSymbolAddress((void**)&cur_u, g_cur_u);
    cudaGetSymbolAddress((void**)&cur_i, g_cur_i);
    cudaGetSymbolAddress((void**)&adj_u, g_adj_u);
    cudaGetSymbolAddress((void**)&adj_i, g_adj_i);
    cudaGetSymbolAddress((void**)&bsum, g_bsum);
    cudaGetSymbolAddress((void**)&wtb, g_wtb);

    cudaFuncSetAttribute(sage_gemm_tc, cudaFuncAttributeMaxDynamicSharedMemorySize,
                         SM_BYTES);

    float* out_u = (float*)d_out;
    float* out_i = out_u + (size_t)NU * DD;

    // weight prep (bf16 hi/lo in ldmatrix block layout)
    prep_weights<<<32, 256>>>(wtb + 0 * 65536, W1r_iu, L1W_u, W1l_iu);
    prep_weights<<<32, 256>>>(wtb + 1 * 65536, W1r_ui, L1W_i, W1l_ui);
    prep_weights<<<32, 256>>>(wtb + 2 * 65536, W2r_iu, L2W_u, W2l_iu);
    prep_weights<<<32, 256>>>(wtb + 3 * 65536, W2r_ui, L2W_i, W2l_ui);

    // CSR build (once; shared by both layers)
    cudaMemsetAsync(deg_u, 0, NU * sizeof(int));
    cudaMemsetAsync(deg_i, 0, NI * sizeof(int));
    count_deg<<<(2 * E + 255) / 256, 256>>>(iu_dst, ui_dst, E, deg_u, deg_i);
    int nbU = (NU + SCAN_B - 1) / SCAN_B, nbI = (NI + SCAN_B - 1) / SCAN_B;
    scan_part<<<nbU + nbI, SCAN_B>>>(deg_u, NU, deg_i, NI, off_u, off_i, bsum, nbU);
    scan_top<<<1, 32>>>(bsum, nbU, nbI, off_u, NU, off_i, NI);
    scan_add<<<(NU + NI + 255) / 256, 256>>>(off_u, cur_u, NU, off_i, cur_i, NI, bsum, nbU);
    fill_adj<<<(2 * E + 255) / 256, 256>>>(iu_src, iu_dst, ui_src, ui_dst, E,
                                           cur_u, adj_u, cur_i, adj_i);

    int gblocks = ((NU + NI) * 32 + 255) / 256;
    gather_agg2<<<gblocks, 256>>>(x_item, adj_u, off_u, sum_u, NU,
                                  x_user, adj_i, off_i, sum_i, NI);

    int gu = (NU + 127) / 128, gi = (NI + 127) / 128;
    sage_gemm_tc<<<gu, 512, SM_BYTES>>>(x_user, sum_u, deg_u, wtb + 0 * 65536,
                                        b1_iu, L1b_u, h1u, NU, 1);
    sage_gemm_tc<<<gi, 512, SM_BYTES>>>(x_item, sum_i, deg_i, wtb + 1 * 65536,
                                        b1_ui, L1b_i, h1i, NI, 1);

    gather_agg2<<<gblocks, 256>>>(h1i, adj_u, off_u, sum_u, NU,
                                  h1u, adj_i, off_i, sum_i, NI);

    sage_gemm_tc<<<gu, 512, SM_BYTES>>>(h1u, sum_u, deg_u, wtb + 2 * 65536,
                                        b2_iu, L2b_u, out_u, NU, 0);
    sage_gemm_tc<<<gi, 512, SM_BYTES>>>(h1i, sum_i, deg_i, wtb + 3 * 65536,
                                        b2_ui, L2b_i, out_i, NI, 0);
}

// round 9
// speedup vs baseline: 2.5626x; 1.1183x over previous
#include <cuda_runtime.h>
#include <cuda_fp16.h>
#include <cstdint>
#include <cstddef>

// Problem constants (fixed by the dataset)
#define NU_MAX 100000
#define NI_MAX 50000
#define E_MAX 300000
#define DD 128
#define SCAN_B 1024

// ---------------- device scratch (no allocations allowed) ----------------
__device__ float g_sum_u[(size_t)NU_MAX * DD];
__device__ float g_sum_i[(size_t)NI_MAX * DD];
__device__ float g_h1u[(size_t)NU_MAX * DD];
__device__ float g_h1i[(size_t)NI_MAX * DD];
__device__ int g_deg_u[NU_MAX];
__device__ int g_deg_i[NI_MAX];
__device__ int g_off_u[NU_MAX + 1];
__device__ int g_off_i[NI_MAX + 1];
__device__ int g_cur_u[NU_MAX];
__device__ int g_cur_i[NI_MAX];
__device__ int g_adj_u[E_MAX];
__device__ int g_adj_i[E_MAX];
__device__ int g_bsum[256];
// fp16 weights, 4 cfgs. Per cfg: [32 kb][128 n][8 k] fp16 = 32768 fp16.
// k global 0..127 = (Wr+LW)^T (X side), 128..255 = Wl^T (mean side).
__device__ __align__(16) __half g_wtb[4 * 32768];

// ---------------- weight prep: combine + fp16 + block layout ----------------
__global__ void prep_weights(__half* __restrict__ dst,
                             const float* __restrict__ Wr,
                             const float* __restrict__ LW,
                             const float* __restrict__ Wl) {
    int kb = blockIdx.x;
    int t = threadIdx.x;
#pragma unroll
    for (int i = 0; i < 4; ++i) {
        int e = i * 256 + t;
        int n = e >> 3, kd = e & 7;
        int k = kb * 8 + kd;
        float v;
        if (k < 128) v = Wr[n * 128 + k] + LW[n * 128 + k];
        else         v = Wl[n * 128 + (k - 128)];
        dst[kb * 1024 + e] = __float2half_rn(v);
    }
}

// ---------------- CSR build ----------------
__global__ void count_deg(const int* __restrict__ iu_dst, const int* __restrict__ ui_dst,
                          int E, int* __restrict__ degU, int* __restrict__ degI) {
    int i = blockIdx.x * blockDim.x + threadIdx.x;
    if (i < E) atomicAdd(&degU[iu_dst[i]], 1);
    else { i -= E; if (i < E) atomicAdd(&degI[ui_dst[i]], 1); }
}

__global__ void scan_part(const int* __restrict__ degU, int nU,
                          const int* __restrict__ degI, int nI,
                          int* __restrict__ offU, int* __restrict__ offI,
                          int* __restrict__ bsum, int nbU) {
    __shared__ int warp_s[32];
    int b = blockIdx.x;
    const int* deg; int* off; int n; int idx0;
    if (b < nbU) { deg = degU; off = offU; n = nU; idx0 = b * SCAN_B; }
    else         { deg = degI; off = offI; n = nI; idx0 = (b - nbU) * SCAN_B; }
    int i = idx0 + threadIdx.x;
    int v = (i < n) ? deg[i] : 0;
    int lane = threadIdx.x & 31, wrp = threadIdx.x >> 5;
    int inc = v;
#pragma unroll
    for (int o = 1; o < 32; o <<= 1) {
        int t = __shfl_up_sync(0xffffffffu, inc, o);
        if (lane >= o) inc += t;
    }
    if (lane == 31) warp_s[wrp] = inc;
    __syncthreads();
    if (wrp == 0) {
        int wv = warp_s[lane];
#pragma unroll
        for (int o = 1; o < 32; o <<= 1) {
            int t = __shfl_up_sync(0xffffffffu, wv, o);
            if (lane >= o) wv += t;
        }
        warp_s[lane] = wv;
    }
    __syncthreads();
    int base = (wrp > 0) ? warp_s[wrp - 1] : 0;
    int excl = base + inc - v;
    if (i < n) off[i] = excl;
    if (threadIdx.x == SCAN_B - 1) bsum[b] = base + inc;
}

__global__ void scan_top(int* __restrict__ bsum, int nbU, int nbI,
                         int* __restrict__ offU, int nU,
                         int* __restrict__ offI, int nI) {
    if (threadIdx.x == 0) {
        int acc = 0;
        for (int i = 0; i < nbU; ++i) { int t = bsum[i]; bsum[i] = acc; acc += t; }
        offU[nU] = acc;
    }
    if (threadIdx.x == 1) {
        int acc = 0;
        for (int i = nbU; i < nbU + nbI; ++i) { int t = bsum[i]; bsum[i] = acc; acc += t; }
        offI[nI] = acc;
    }
}

__global__ void scan_add(int* __restrict__ offU, int* __restrict__ curU, int nU,
                         int* __restrict__ offI, int* __restrict__ curI, int nI,
                         const int* __restrict__ bsum, int nbU) {
    int i = blockIdx.x * blockDim.x + threadIdx.x;
    if (i < nU) {
        int v = offU[i] + bsum[i / SCAN_B];
        offU[i] = v; curU[i] = v;
    } else {
        i -= nU;
        if (i < nI) {
            int v = offI[i] + bsum[nbU + i / SCAN_B];
            offI[i] = v; curI[i] = v;
        }
    }
}

__global__ void fill_adj(const int* __restrict__ iu_src, const int* __restrict__ iu_dst,
                         const int* __restrict__ ui_src, const int* __restrict__ ui_dst,
                         int E, int* __restrict__ curU, int* __restrict__ adjU,
                         int* __restrict__ curI, int* __restrict__ adjI) {
    int i = blockIdx.x * blockDim.x + threadIdx.x;
    if (i < E) {
        int p = atomicAdd(&curU[iu_dst[i]], 1);
        adjU[p] = iu_src[i];
    } else {
        i -= E;
        if (i < E) {
            int p = atomicAdd(&curI[ui_dst[i]], 1);
            adjI[p] = ui_src[i];
        }
    }
}

// ---------------- gather aggregation (one warp per dst; MLP=4 unrolled) -----
__global__ void gather_agg2(const float* __restrict__ srcU, const int* __restrict__ adjU,
                            const int* __restrict__ offU, float* __restrict__ outU, int nU,
                            const float* __restrict__ srcI, const int* __restrict__ adjI,
                            const int* __restrict__ offI, float* __restrict__ outI, int nI) {
    int w = (blockIdx.x * blockDim.x + threadIdx.x) >> 5;
    int lane = threadIdx.x & 31;
    const float* feat; const int* adj; const int* off; float* out; int d;
    if (w < nU) { feat = srcU; adj = adjU; off = offU; out = outU; d = w; }
    else {
        w -= nU;
        if (w >= nI) return;
        feat = srcI; adj = adjI; off = offI; out = outI; d = w;
    }
    int beg = __ldg(off + d), end = __ldg(off + d + 1);
    float4 a0 = make_float4(0.f, 0.f, 0.f, 0.f);
    float4 a1 = make_float4(0.f, 0.f, 0.f, 0.f);
    int base = beg;
    for (; base + 4 <= end; base += 4) {
        int s0 = __ldg(adj + base + 0);
        int s1 = __ldg(adj + base + 1);
        int s2 = __ldg(adj + base + 2);
        int s3 = __ldg(adj + base + 3);
        float4 v0 = *(const float4*)(feat + (size_t)s0 * DD + lane * 4);
        float4 v1 = *(const float4*)(feat + (size_t)s1 * DD + lane * 4);
        float4 v2 = *(const float4*)(feat + (size_t)s2 * DD + lane * 4);
        float4 v3 = *(const float4*)(feat + (size_t)s3 * DD + lane * 4);
        a0.x += v0.x + v1.x; a0.y += v0.y + v1.y;
        a0.z += v0.z + v1.z; a0.w += v0.w + v1.w;
        a1.x += v2.x + v3.x; a1.y += v2.y + v3.y;
        a1.z += v2.z + v3.z; a1.w += v2.w + v3.w;
    }
    for (; base < end; ++base) {
        int s = __ldg(adj + base);
        float4 v = *(const float4*)(feat + (size_t)s * DD + lane * 4);
        a0.x += v.x; a0.y += v.y; a0.z += v.z; a0.w += v.w;
    }
    a0.x += a1.x; a0.y += a1.y; a0.z += a1.z; a0.w += a1.w;
    *(float4*)(out + (size_t)d * DD + lane * 4) = a0;
}

// ---------------- tensor-core fused SAGE GEMM (fp16 2-term split) ----------
// out[m,:] = act( X[m,:] @ Wc^T + (1/max(deg,1)) * S[m,:] @ Wl^T + b1 + b2 )
// A = Ah + Al (fp16 split); W = fp16(W). acc += AhW + AlW (fp32 accum).
__device__ __forceinline__ void ldsm4(uint32_t* r, const void* p) {
    uint32_t a = (uint32_t)__cvta_generic_to_shared(p);
    asm volatile("ldmatrix.sync.aligned.m8n8.x4.shared.b16 {%0,%1,%2,%3}, [%4];\n"
                 : "=r"(r[0]), "=r"(r[1]), "=r"(r[2]), "=r"(r[3]) : "r"(a));
}
__device__ __forceinline__ void mma16816(float* c, const uint32_t* a, const uint32_t* b) {
    asm volatile("mma.sync.aligned.m16n8k16.row.col.f32.f16.f16.f32 "
                 "{%0,%1,%2,%3}, {%4,%5,%6,%7}, {%8,%9}, {%0,%1,%2,%3};\n"
                 : "+f"(c[0]), "+f"(c[1]), "+f"(c[2]), "+f"(c[3])
                 : "r"(a[0]), "r"(a[1]), "r"(a[2]), "r"(a[3]), "r"(b[0]), "r"(b[1]));
}
__device__ __forceinline__ void cp_async16(void* smem_dst, const void* gsrc) {
    uint32_t a = (uint32_t)__cvta_generic_to_shared(smem_dst);
    asm volatile("cp.async.cg.shared.global [%0], [%1], 16;\n"
                 :: "r"(a), "l"(gsrc) : "memory");
}
#define CP_ASYNC_COMMIT() asm volatile("cp.async.commit_group;\n" ::: "memory")
#define CP_ASYNC_WAIT0()  asm volatile("cp.async.wait_group 0;\n" ::: "memory")

// smem: W 2 stages x 4096 fp16 = 16384 B
//       A 2 stages x (hi 4096 + lo 4096) fp16 = 32768 B  (at 16384)
//       scs 128 f32 (at 49152), bss 128 f32 (at 49664)
#define SM_BYTES 50176

__global__ __launch_bounds__(512, 1)
void sage_gemm_tc(const float* __restrict__ X, const float* __restrict__ S,
                  const int* __restrict__ deg, const __half* __restrict__ Wt,
                  const float* __restrict__ b1, const float* __restrict__ b2,
                  float* __restrict__ out, int nrows, int do_relu) {
    extern __shared__ char sm_raw[];
    __half* Wsm = (__half*)sm_raw;                    // 2 stages x 4096
    __half* Asm = (__half*)(sm_raw + 16384);          // 2 stages x 8192 (hi+lo)
    float* scs = (float*)(sm_raw + 49152);
    float* bss = (float*)(sm_raw + 49664);

    const int tid = threadIdx.x;
    const int lane = tid & 31;
    const int wid = tid >> 5;              // 0..15
    const int m0w = (wid & 3) * 32;        // warp m-origin
    const int n0w = (wid >> 2) * 32;       // warp n-origin
    const int m0 = blockIdx.x * 128;

    // ldmatrix per-lane geometry
    const int sel = lane >> 3, lr = lane & 7;
    const int a_ro = ((sel & 1) << 3) + lr;
    const int a_kb = sel >> 1;
    const int b_ro = ((sel >> 1) << 3) + lr;
    const int b_kb = sel & 1;

    const int arow = tid >> 2;   // A loader: row 0..127
    const int aq = tid & 3;      // A loader: 8-float quarter (one kb)

    if (tid < 128) {
        int c = (m0 + tid < nrows) ? deg[m0 + tid] : 1;
        scs[tid] = 1.0f / fmaxf((float)c, 1.0f);
        bss[tid] = b1[tid] + b2[tid];
    }

    float acc[2][4][4];
#pragma unroll
    for (int i = 0; i < 2; ++i)
#pragma unroll
        for (int j = 0; j < 4; ++j)
#pragma unroll
            for (int q = 0; q < 4; ++q) acc[i][j][q] = 0.f;

    float4 pfA[2];

    // W chunk c -> stage st via cp.async (8 KB; 512 thr x 16 B)
    auto loadW = [&](int c, int st) {
        const char* sh = (const char*)(Wt + c * 4096) + tid * 16;
        char* dh = (char*)(Wsm + st * 4096) + tid * 16;
        cp_async16(dh, sh);
        CP_ASYNC_COMMIT();
    };
    // A chunk c: load 8 floats into regs
    auto loadA = [&](int c) {
        const float* src = (c < 4) ? X : S;
        int kc = (c & 3) * 32 + aq * 8;
        if (m0 + arow < nrows) {
            const float* row = src + (size_t)(m0 + arow) * DD + kc;
            pfA[0] = *(const float4*)(row);
            pfA[1] = *(const float4*)(row + 4);
        } else {
            pfA[0] = make_float4(0.f, 0.f, 0.f, 0.f);
            pfA[1] = make_float4(0.f, 0.f, 0.f, 0.f);
        }
    };
    // A: fp32 -> fp16 hi/lo into block layout [kb 4][row 128][kd 8]
    auto storeA = [&](int c, int st) {
        float s = (c >= 4) ? scs[arow] : 1.0f;
        __half* ab = Asm + st * 8192;
        int idx = (aq * 128 + arow) * 8;
        uint32_t hv[4], lv[4];
#pragma unroll
        for (int h = 0; h < 2; ++h) {
            float4 v = pfA[h];
            v.x *= s; v.y *= s; v.z *= s; v.w *= s;
            __half2 h0 = __floats2half2_rn(v.x, v.y);
            __half2 h1 = __floats2half2_rn(v.z, v.w);
            hv[h * 2 + 0] = *(uint32_t*)&h0;
            hv[h * 2 + 1] = *(uint32_t*)&h1;
            __half2 l0 = __floats2half2_rn(v.x - __half2float(h0.x),
                                           v.y - __half2float(h0.y));
            __half2 l1 = __floats2half2_rn(v.z - __half2float(h1.x),
                                           v.w - __half2float(h1.y));
            lv[h * 2 + 0] = *(uint32_t*)&l0;
            lv[h * 2 + 1] = *(uint32_t*)&l1;
        }
        *(uint4*)(ab + idx) = make_uint4(hv[0], hv[1], hv[2], hv[3]);
        *(uint4*)(ab + 4096 + idx) = make_uint4(lv[0], lv[1], lv[2], lv[3]);
    };

    loadW(0, 0);
    loadA(0);
    storeA(0, 0);
    CP_ASYNC_WAIT0();
    __syncthreads();

    for (int c = 0; c < 8; ++c) {
        int st = c & 1;
        if (c < 7) { loadW(c + 1, 1 - st); loadA(c + 1); }
#pragma unroll
        for (int kk = 0; kk < 2; ++kk) {
            uint32_t ah[2][4], al[2][4], bh[2][4];
#pragma unroll
            for (int mt = 0; mt < 2; ++mt) {
                const __half* p = Asm + st * 8192 +
                    (((2 * kk + a_kb) * 128) + m0w + mt * 16 + a_ro) * 8;
                ldsm4(ah[mt], p);
                ldsm4(al[mt], p + 4096);
            }
#pragma unroll
            for (int ng = 0; ng < 2; ++ng) {
                const __half* p = Wsm + st * 4096 +
                    (((2 * kk + b_kb) * 128) + n0w + ng * 16 + b_ro) * 8;
                ldsm4(bh[ng], p);
            }
#pragma unroll
            for (int mt = 0; mt < 2; ++mt)
#pragma unroll
                for (int nt = 0; nt < 4; ++nt) {
                    const uint32_t* pbh = &bh[nt >> 1][(nt & 1) * 2];
                    mma16816(acc[mt][nt], ah[mt], pbh);
                    mma16816(acc[mt][nt], al[mt], pbh);
                }
        }
        if (c < 7) {
            storeA(c + 1, 1 - st);
            CP_ASYNC_WAIT0();
            __syncthreads();
        }
    }

    // epilogue: bias (+ optional relu), guarded float2 stores
#pragma unroll
    for (int mt = 0; mt < 2; ++mt) {
        int rbase = m0w + mt * 16 + (lane >> 2);
#pragma unroll
        for (int half = 0; half < 2; ++half) {
            int r = rbase + half * 8;
            if (m0 + r >= nrows) continue;
            float* orow = out + (size_t)(m0 + r) * DD;
#pragma unroll
            for (int nt = 0; nt < 4; ++nt) {
                int col = n0w + nt * 8 + (lane & 3) * 2;
                float v0 = acc[mt][nt][half * 2 + 0] + bss[col];
                float v1 = acc[mt][nt][half * 2 + 1] + bss[col + 1];
                if (do_relu) { v0 = fmaxf(v0, 0.f); v1 = fmaxf(v1, 0.f); }
                *(float2*)(orow + col) = make_float2(v0, v1);
            }
        }
    }
}

// ---------------- host orchestration ----------------
extern "C" void kernel_launch(void* const* d_in, const int* in_sizes, int n_in,
                              void* d_out, int out_size) {
    const float* x_user = (const float*)d_in[0];
    const float* x_item = (const float*)d_in[1];
    const int* ui_src = (const int*)d_in[2];
    const int* ui_dst = (const int*)d_in[3];
    const int* iu_src = (const int*)d_in[4];
    const int* iu_dst = (const int*)d_in[5];
    const float* W1l_ui = (const float*)d_in[6];
    const float* b1_ui  = (const float*)d_in[7];
    const float* W1r_ui = (const float*)d_in[8];
    const float* W1l_iu = (const float*)d_in[9];
    const float* b1_iu  = (const float*)d_in[10];
    const float* W1r_iu = (const float*)d_in[11];
    const float* L1W_u  = (const float*)d_in[12];
    const float* L1b_u  = (const float*)d_in[13];
    const float* L1W_i  = (const float*)d_in[14];
    const float* L1b_i  = (const float*)d_in[15];
    const float* W2l_ui = (const float*)d_in[16];
    const float* b2_ui  = (const float*)d_in[17];
    const float* W2r_ui = (const float*)d_in[18];
    const float* W2l_iu = (const float*)d_in[19];
    const float* b2_iu  = (const float*)d_in[20];
    const float* W2r_iu = (const float*)d_in[21];
    const float* L2W_u  = (const float*)d_in[22];
    const float* L2b_u  = (const float*)d_in[23];
    const float* L2W_i  = (const float*)d_in[24];
    const float* L2b_i  = (const float*)d_in[25];

    const int NU = in_sizes[0] / DD;
    const int NI = in_sizes[1] / DD;
    const int E = in_sizes[2];

    float *sum_u, *sum_i, *h1u, *h1i;
    int *deg_u, *deg_i, *off_u, *off_i, *cur_u, *cur_i, *adj_u, *adj_i, *bsum;
    __half* wtb;
    cudaGetSymbolAddress((void**)&sum_u, g_sum_u);
    cudaGetSymbolAddress((void**)&sum_i, g_sum_i);
    cudaGetSymbolAddress((void**)&h1u, g_h1u);
    cudaGetSymbolAddress((void**)&h1i, g_h1i);
    cudaGetSymbolAddress((void**)&deg_u, g_deg_u);
    cudaGetSymbolAddress((void**)&deg_i, g_deg_i);
    cudaGetSymbolAddress((void**)&off_u, g_off_u);
    cudaGetSymbolAddress((void**)&off_i, g_off_i);
    cudaGetSymbolAddress((void**)&cur_u, g_cur_u);
    cudaGetSymbolAddress((void**)&cur_i, g_cur_i);
    cudaGetSymbolAddress((void**)&adj_u, g_adj_u);
    cudaGetSymbolAddress((void**)&adj_i, g_adj_i);
    cudaGetSymbolAddress((void**)&bsum, g_bsum);
    cudaGetSymbolAddress((void**)&wtb, g_wtb);

    cudaFuncSetAttribute(sage_gemm_tc, cudaFuncAttributeMaxDynamicSharedMemorySize,
                         SM_BYTES);

    float* out_u = (float*)d_out;
    float* out_i = out_u + (size_t)NU * DD;

    // weight prep (fp16, ldmatrix block layout)
    prep_weights<<<32, 256>>>(wtb + 0 * 32768, W1r_iu, L1W_u, W1l_iu);
    prep_weights<<<32, 256>>>(wtb + 1 * 32768, W1r_ui, L1W_i, W1l_ui);
    prep_weights<<<32, 256>>>(wtb + 2 * 32768, W2r_iu, L2W_u, W2l_iu);
    prep_weights<<<32, 256>>>(wtb + 3 * 32768, W2r_ui, L2W_i, W2l_ui);

    // CSR build (once; shared by both layers)
    cudaMemsetAsync(deg_u, 0, NU * sizeof(int));
    cudaMemsetAsync(deg_i, 0, NI * sizeof(int));
    count_deg<<<(2 * E + 255) / 256, 256>>>(iu_dst, ui_dst, E, deg_u, deg_i);
    int nbU = (NU + SCAN_B - 1) / SCAN_B, nbI = (NI + SCAN_B - 1) / SCAN_B;
    scan_part<<<nbU + nbI, SCAN_B>>>(deg_u, NU, deg_i, NI, off_u, off_i, bsum, nbU);
    scan_top<<<1, 32>>>(bsum, nbU, nbI, off_u, NU, off_i, NI);
    scan_add<<<(NU + NI + 255) / 256, 256>>>(off_u, cur_u, NU, off_i, cur_i, NI, bsum, nbU);
    fill_adj<<<(2 * E + 255) / 256, 256>>>(iu_src, iu_dst, ui_src, ui_dst, E,
                                           cur_u, adj_u, cur_i, adj_i);

    int gblocks = ((NU + NI) * 32 + 255) / 256;
    gather_agg2<<<gblocks, 256>>>(x_item, adj_u, off_u, sum_u, NU,
                                  x_user, adj_i, off_i, sum_i, NI);

    int gu = (NU + 127) / 128, gi = (NI + 127) / 128;
    sage_gemm_tc<<<gu, 512, SM_BYTES>>>(x_user, sum_u, deg_u, wtb + 0 * 32768,
                                        b1_iu, L1b_u, h1u, NU, 1);
    sage_gemm_tc<<<gi, 512, SM_BYTES>>>(x_item, sum_i, deg_i, wtb + 1 * 32768,
                                        b1_ui, L1b_i, h1i, NI, 1);

    gather_agg2<<<gblocks, 256>>>(h1i, adj_u, off_u, sum_u, NU,
                                  h1u, adj_i, off_i, sum_i, NI);

    sage_gemm_tc<<<gu, 512, SM_BYTES>>>(h1u, sum_u, deg_u, wtb + 2 * 32768,
                                        b2_iu, L2b_u, out_u, NU, 0);
    sage_gemm_tc<<<gi, 512, SM_BYTES>>>(h1i, sum_i, deg_i, wtb + 3 * 32768,
                                        b2_ui, L2b_i, out_i, NI, 0);
}